// round 1
// baseline (speedup 1.0000x reference)
#include <cuda_runtime.h>
#include <math.h>

#define BB 32
#define HWT 12544          // 112*112
#define CC 256
#define HID 32
#define CHUNKS 32
#define ROWS_PER_CHUNK (HWT / CHUNKS)     // 392
#define RG 4
#define ROWS_PER_RG (ROWS_PER_CHUNK / RG) // 98
#define NPART (CHUNKS * RG)               // 128 partials per (b,c)
#define F4_PER_ROW (CC / 4)               // 64
#define F4_PER_B ((size_t)HWT * F4_PER_ROW)   // 802816
#define BLOCKS3 98
#define F4_PER_BLOCK3 (F4_PER_B / BLOCKS3)    // 8192

__device__ float g_psum[BB][NPART][CC];
__device__ float g_pmax[BB][NPART][CC];
__device__ float g_scale[BB][CC];

// Kernel 1: partial sum/max pooling. grid (CHUNKS, B), 256 threads.
// Thread = (rg, c4): one float4 channel group, 98 rows. LDG.128 coalesced:
// a warp's 32 lanes cover 512B contiguous; 2 warps cover the 1KB channel row.
__global__ void __launch_bounds__(256) pool_kernel(const float* __restrict__ x) {
    const int b = blockIdx.y;
    const int chunk = blockIdx.x;
    const int tid = threadIdx.x;
    const int c4 = tid & 63;
    const int rg = tid >> 6;

    const size_t row0 = (size_t)b * HWT + (size_t)chunk * ROWS_PER_CHUNK + (size_t)rg * ROWS_PER_RG;
    const float4* __restrict__ xp = reinterpret_cast<const float4*>(x) + row0 * F4_PER_ROW + c4;

    float4 s = make_float4(0.f, 0.f, 0.f, 0.f);
    float4 m = make_float4(-INFINITY, -INFINITY, -INFINITY, -INFINITY);
    #pragma unroll 7
    for (int r = 0; r < ROWS_PER_RG; ++r) {
        float4 v = xp[(size_t)r * F4_PER_ROW];
        s.x += v.x; s.y += v.y; s.z += v.z; s.w += v.w;
        m.x = fmaxf(m.x, v.x); m.y = fmaxf(m.y, v.y);
        m.z = fmaxf(m.z, v.z); m.w = fmaxf(m.w, v.w);
    }
    const int p = chunk * RG + rg;
    reinterpret_cast<float4*>(&g_psum[b][p][0])[c4] = s;
    reinterpret_cast<float4*>(&g_pmax[b][p][0])[c4] = m;
}

// Kernel 2: final reduction + dual-branch MLP + sigmoid. grid (B), 256 threads.
__global__ void __launch_bounds__(256) mlp_kernel(const float* __restrict__ w1,
                                                  const float* __restrict__ b1,
                                                  const float* __restrict__ w2,
                                                  const float* __restrict__ b2) {
    const int b = blockIdx.x;
    const int c = threadIdx.x;

    float s = 0.f;
    float m = -INFINITY;
    #pragma unroll 8
    for (int p = 0; p < NPART; ++p) {
        s += g_psum[b][p][c];
        m = fmaxf(m, g_pmax[b][p][c]);
    }

    __shared__ float s_avg[CC];
    __shared__ float s_max[CC];
    __shared__ float s_h[2 * HID];
    s_avg[c] = s * (1.0f / (float)HWT);
    s_max[c] = m;
    __syncthreads();

    // Hidden layer: threads 0..31 = avg branch, 32..63 = max branch.
    if (c < 2 * HID) {
        const int j = c & (HID - 1);
        const float* pool = (c < HID) ? s_avg : s_max;
        float acc = b1[j];
        #pragma unroll 8
        for (int i = 0; i < CC; ++i)
            acc += pool[i] * w1[i * HID + j];
        s_h[c] = fmaxf(acc, 0.f);
    }
    __syncthreads();

    // Output layer: out = (hA @ w2 + b2) + (hM @ w2 + b2) = 2*b2 + (hA+hM) @ w2
    float acc = 2.0f * b2[c];
    #pragma unroll
    for (int j = 0; j < HID; ++j)
        acc += (s_h[j] + s_h[HID + j]) * w2[j * CC + c];
    g_scale[b][c] = 1.0f / (1.0f + expf(-acc));
}

// Kernel 3: out = x * scale[b,c]. grid (BLOCKS3, B), 256 threads, 32 float4/thread.
// Per-thread scale float4 is loop-invariant: (base + i) % 64 == tid % 64.
__global__ void __launch_bounds__(256) scale_kernel(const float* __restrict__ x,
                                                    float* __restrict__ out) {
    const int b = blockIdx.y;
    const int tid = threadIdx.x;
    const float4 sc = reinterpret_cast<const float4*>(&g_scale[b][0])[tid & 63];

    const size_t base = (size_t)b * F4_PER_B + (size_t)blockIdx.x * F4_PER_BLOCK3;
    const float4* __restrict__ xi = reinterpret_cast<const float4*>(x) + base;
    float4* __restrict__ xo = reinterpret_cast<float4*>(out) + base;

    #pragma unroll 8
    for (int i = tid; i < F4_PER_BLOCK3; i += 256) {
        float4 v = xi[i];
        v.x *= sc.x; v.y *= sc.y; v.z *= sc.z; v.w *= sc.w;
        xo[i] = v;
    }
}

extern "C" void kernel_launch(void* const* d_in, const int* in_sizes, int n_in,
                              void* d_out, int out_size) {
    const float* x  = (const float*)d_in[0];
    const float* w1 = (const float*)d_in[1];
    const float* b1 = (const float*)d_in[2];
    const float* w2 = (const float*)d_in[3];
    const float* b2 = (const float*)d_in[4];
    float* out = (float*)d_out;

    pool_kernel<<<dim3(CHUNKS, BB), 256>>>(x);
    mlp_kernel<<<BB, 256>>>(w1, b1, w2, b2);
    scale_kernel<<<dim3(BLOCKS3, BB), 256>>>(x, out);
}